// round 13
// baseline (speedup 1.0000x reference)
#include <cuda_runtime.h>
#include <cuda_bf16.h>
#include <cstdint>

#define MAXN 10000
#define MAXE 320000
#define IN_DIM 512
#define H1 256
#define H2 128

// ---------------- scratch (device globals; no allocation allowed) ----------------
__device__ int   g_deg_out[MAXN];
__device__ int   g_deg_in[MAXN];
__device__ int   g_cnt[MAXN];
__device__ int   g_alloc;
__device__ float g_rs_out[MAXN];
__device__ float g_rs_in[MAXN];
__device__ int   g_row_off[MAXN];
__device__ int   g_perm_src[MAXE];
__device__ float g_y1[MAXN * H1];    // (x*rs_out) @ W1
__device__ float g_y23[MAXN * H1];   // (h*rs_out) @ [W2|W3]
__device__ __align__(16) __nv_bfloat16 g_ha_hi[MAXN * H1];  // (h*rs_out) bf16 hi
__device__ __align__(16) __nv_bfloat16 g_ha_lo[MAXN * H1];  // (h*rs_out) bf16 lo
__device__ __align__(16) __nv_bfloat16 g_w1t_hi[H1 * IN_DIM];   // W1^T [256][512]
__device__ __align__(16) __nv_bfloat16 g_w1t_lo[H1 * IN_DIM];
__device__ __align__(16) __nv_bfloat16 g_w23t_hi[H1 * H1];      // [W2|W3]^T [256][256]
__device__ __align__(16) __nv_bfloat16 g_w23t_lo[H1 * H1];
__device__ __align__(16) __nv_bfloat16 g_zhi[MAXN * H2];
__device__ __align__(16) __nv_bfloat16 g_zlo[MAXN * H2];

// ---------------- helpers ----------------
__device__ __forceinline__ float sigm(float x) {
    return 1.0f / (1.0f + __expf(-x));
}
__device__ __forceinline__ void bsplit(float v, __nv_bfloat16& hi, __nv_bfloat16& lo) {
    hi = __float2bfloat16(v);
    lo = __float2bfloat16(v - __bfloat162float(hi));
}
__device__ __forceinline__ uint32_t smem_u32(const void* p) {
    uint32_t a;
    asm("{ .reg .u64 t; cvta.to.shared.u64 t, %1; cvt.u32.u64 %0, t; }" : "=r"(a) : "l"(p));
    return a;
}
__device__ __forceinline__ void ldsm_x4(uint32_t a[4], uint32_t addr) {
    asm volatile("ldmatrix.sync.aligned.m8n8.x4.shared.b16 {%0,%1,%2,%3}, [%4];"
        : "=r"(a[0]), "=r"(a[1]), "=r"(a[2]), "=r"(a[3]) : "r"(addr));
}
__device__ __forceinline__ void ldsm_x2(uint32_t b[2], uint32_t addr) {
    asm volatile("ldmatrix.sync.aligned.m8n8.x2.shared.b16 {%0,%1}, [%2];"
        : "=r"(b[0]), "=r"(b[1]) : "r"(addr));
}
__device__ __forceinline__ void mma_bf16(float d[4], const uint32_t a[4], const uint32_t b[2]) {
    asm volatile("mma.sync.aligned.m16n8k16.row.col.f32.bf16.bf16.f32 "
        "{%0,%1,%2,%3}, {%4,%5,%6,%7}, {%8,%9}, {%0,%1,%2,%3};"
        : "+f"(d[0]), "+f"(d[1]), "+f"(d[2]), "+f"(d[3])
        : "r"(a[0]), "r"(a[1]), "r"(a[2]), "r"(a[3]), "r"(b[0]), "r"(b[1]));
}
__device__ __forceinline__ uint32_t pack_bf2(__nv_bfloat16 a, __nv_bfloat16 b) {
    __nv_bfloat162 v(a, b);
    return *(uint32_t*)&v;
}
// packed f32x2 FMA helpers (FFMA2 decoder path)
__device__ __forceinline__ unsigned long long pack_dup(float a) {
    unsigned long long r;
    unsigned int ai = __float_as_uint(a);
    asm("mov.b64 %0, {%1, %1};" : "=l"(r) : "r"(ai));
    return r;
}
__device__ __forceinline__ unsigned long long pack2f(float x, float y) {
    unsigned long long r;
    asm("mov.b64 %0, {%1, %2};" : "=l"(r) : "r"(__float_as_uint(x)), "r"(__float_as_uint(y)));
    return r;
}
__device__ __forceinline__ void ffma2(unsigned long long& d, unsigned long long a, unsigned long long b) {
    asm("fma.rn.f32x2 %0, %1, %2, %3;" : "=l"(d) : "l"(a), "l"(b), "l"(d));
}
__device__ __forceinline__ float2 unpack2f(unsigned long long v) {
    unsigned int lo, hi;
    asm("mov.b64 {%0, %1}, %2;" : "=r"(lo), "=r"(hi) : "l"(v));
    return make_float2(__uint_as_float(lo), __uint_as_float(hi));
}
// two packed bf16 pairs (hi,lo) -> two fp32 values hi+lo
__device__ __forceinline__ void bf2x_to_f2(uint32_t h, uint32_t l, float& a, float& b) {
    __nv_bfloat162 H = *(__nv_bfloat162*)&h;
    __nv_bfloat162 L = *(__nv_bfloat162*)&l;
    a = __bfloat162float(H.x) + __bfloat162float(L.x);
    b = __bfloat162float(H.y) + __bfloat162float(L.y);
}

// ---------------- small setup kernels ----------------
__global__ void zero_kernel(int n) {
    int i = blockIdx.x * blockDim.x + threadIdx.x;
    if (i < n) { g_deg_out[i] = 0; g_deg_in[i] = 0; g_cnt[i] = 0; }
    if (i == 0) g_alloc = 0;
}

__global__ void degree_kernel(const int* __restrict__ src, const int* __restrict__ dst, int e) {
    int i = blockIdx.x * blockDim.x + threadIdx.x;
    if (i < e) {
        atomicAdd(&g_deg_out[src[i]], 1);
        atomicAdd(&g_deg_in[dst[i]], 1);
    }
}

__global__ void rs_alloc_kernel(int n) {
    int i = blockIdx.x * blockDim.x + threadIdx.x;
    if (i < n) {
        int dIn = g_deg_in[i];
        g_rs_out[i] = rsqrtf(fmaxf((float)g_deg_out[i], 1.0f));
        g_rs_in[i]  = rsqrtf(fmaxf((float)dIn, 1.0f));
        g_row_off[i] = atomicAdd(&g_alloc, dIn);
    }
}

__global__ void perm_kernel(const int* __restrict__ src, const int* __restrict__ dst, int e) {
    int i = blockIdx.x * blockDim.x + threadIdx.x;
    if (i < e) {
        int d = dst[i];
        int pos = atomicAdd(&g_cnt[d], 1);
        g_perm_src[g_row_off[d] + pos] = src[i];
    }
}

// one-shot weight transpose + bf16 hi/lo split
__global__ void convw_kernel(const float* __restrict__ W1, const float* __restrict__ W2,
                             const float* __restrict__ W3) {
    int idx = blockIdx.x * blockDim.x + threadIdx.x;
    if (idx < H1 * IN_DIM) {
        int nn = idx >> 9, k = idx & 511;
        __nv_bfloat16 hi, lo;
        bsplit(W1[k * H1 + nn], hi, lo);
        g_w1t_hi[idx] = hi;
        g_w1t_lo[idx] = lo;
    } else {
        int j = idx - H1 * IN_DIM;
        if (j < H1 * H1) {
            int nn = j >> 8, k = j & 255;
            float v = (nn < H2) ? W2[k * H2 + nn] : W3[k * H2 + (nn - H2)];
            __nv_bfloat16 hi, lo;
            bsplit(v, hi, lo);
            g_w23t_hi[j] = hi;
            g_w23t_lo[j] = lo;
        }
    }
}

// ---------------- HMMA GEMM smem geometry ----------------
#define ROWB_G 144
#define GBUF (128 * ROWB_G)
#define GA_HI 0
#define GA_LO GBUF
#define GB_HI (2 * GBUF)
#define GB_LO (3 * GBUF)
#define G_TOTAL (4 * GBUF)             // 73728

// ---------------- GEMM1: y1 = (X*rs_out) @ W1 ----------------
__global__ void __launch_bounds__(256) gemm1_hmma(const float* __restrict__ X, int M) {
    extern __shared__ char smem_raw[];
    int tid = threadIdx.x;
    int w = tid >> 5, lane = tid & 31;
    int m0 = blockIdx.x * 128, n0 = blockIdx.y * 128;
    uint32_t smb = smem_u32(smem_raw);
    int warp_m = w & 1, warp_n = w >> 1;
    uint32_t aoffA = (uint32_t)((warp_m * 64 + (lane & 15)) * ROWB_G + (lane >> 4) * 16);
    uint32_t aoffB = (uint32_t)((warp_n * 32 + (lane & 7)) * ROWB_G + ((lane >> 3) & 1) * 16);

    float acc[4][4][4] = {};

    for (int ch = 0; ch < IN_DIM / 64; ch++) {
        int k0 = ch * 64;
        __syncthreads();
#pragma unroll
        for (int q = 0; q < 8; q++) {
            int idx = q * 256 + tid;
            int row = idx >> 4, c4 = (idx & 15) * 4;
            int gi = m0 + row;
            float4 v = make_float4(0.f, 0.f, 0.f, 0.f);
            float ro = 0.f;
            if (gi < M) { v = *(const float4*)&X[gi * IN_DIM + k0 + c4]; ro = g_rs_out[gi]; }
            __nv_bfloat16 h0, l0, h1, l1, h2, l2, h3, l3;
            bsplit(v.x * ro, h0, l0); bsplit(v.y * ro, h1, l1);
            bsplit(v.z * ro, h2, l2); bsplit(v.w * ro, h3, l3);
            int off = row * ROWB_G + c4 * 2;
            *(uint2*)(smem_raw + GA_HI + off) = make_uint2(pack_bf2(h0, h1), pack_bf2(h2, h3));
            *(uint2*)(smem_raw + GA_LO + off) = make_uint2(pack_bf2(l0, l1), pack_bf2(l2, l3));
        }
#pragma unroll
        for (int q = 0; q < 4; q++) {
            int idx = q * 256 + tid;
            int row = idx >> 3, seg = (idx & 7);
            int off = row * ROWB_G + seg * 16;
            *(uint4*)(smem_raw + GB_HI + off) = *(const uint4*)&g_w1t_hi[(n0 + row) * IN_DIM + k0 + seg * 8];
            *(uint4*)(smem_raw + GB_LO + off) = *(const uint4*)&g_w1t_lo[(n0 + row) * IN_DIM + k0 + seg * 8];
        }
        __syncthreads();
#pragma unroll
        for (int ks = 0; ks < 4; ks++) {
            uint32_t k2 = (uint32_t)(ks * 32);
            uint32_t Ahi[4][4], Bhi[4][2], Blo[4][2];
#pragma unroll
            for (int mf = 0; mf < 4; mf++)
                ldsm_x4(Ahi[mf], smb + GA_HI + aoffA + mf * (16 * ROWB_G) + k2);
#pragma unroll
            for (int nf = 0; nf < 4; nf++) {
                ldsm_x2(Bhi[nf], smb + GB_HI + aoffB + nf * (8 * ROWB_G) + k2);
                ldsm_x2(Blo[nf], smb + GB_LO + aoffB + nf * (8 * ROWB_G) + k2);
            }
#pragma unroll
            for (int mf = 0; mf < 4; mf++)
#pragma unroll
                for (int nf = 0; nf < 4; nf++) {
                    mma_bf16(acc[mf][nf], Ahi[mf], Bhi[nf]);
                    mma_bf16(acc[mf][nf], Ahi[mf], Blo[nf]);
                }
            uint32_t Alo[4][4];
#pragma unroll
            for (int mf = 0; mf < 4; mf++)
                ldsm_x4(Alo[mf], smb + GA_LO + aoffA + mf * (16 * ROWB_G) + k2);
#pragma unroll
            for (int mf = 0; mf < 4; mf++)
#pragma unroll
                for (int nf = 0; nf < 4; nf++)
                    mma_bf16(acc[mf][nf], Alo[mf], Bhi[nf]);
        }
    }
    int g = lane >> 2, q = lane & 3;
#pragma unroll
    for (int mf = 0; mf < 4; mf++)
#pragma unroll
        for (int rr = 0; rr < 2; rr++) {
            int i = m0 + warp_m * 64 + mf * 16 + g + rr * 8;
            if (i < M) {
#pragma unroll
                for (int nf = 0; nf < 4; nf++) {
                    int j = n0 + warp_n * 32 + nf * 8 + q * 2;
                    *(float2*)&g_y1[i * H1 + j] =
                        make_float2(acc[mf][nf][rr * 2], acc[mf][nf][rr * 2 + 1]);
                }
            }
        }
}

// ---------------- GEMM23: y23 = (h*rs_out) @ [W2|W3] ----------------
__global__ void __launch_bounds__(256) gemm23_hmma(int M) {
    extern __shared__ char smem_raw[];
    int tid = threadIdx.x;
    int w = tid >> 5, lane = tid & 31;
    int m0 = blockIdx.x * 128, n0 = blockIdx.y * 128;
    uint32_t smb = smem_u32(smem_raw);
    int warp_m = w & 1, warp_n = w >> 1;
    uint32_t aoffA = (uint32_t)((warp_m * 64 + (lane & 15)) * ROWB_G + (lane >> 4) * 16);
    uint32_t aoffB = (uint32_t)((warp_n * 32 + (lane & 7)) * ROWB_G + ((lane >> 3) & 1) * 16);

    float acc[4][4][4] = {};
    const uint4 zz = make_uint4(0u, 0u, 0u, 0u);

    for (int ch = 0; ch < H1 / 64; ch++) {
        int k0 = ch * 64;
        __syncthreads();
#pragma unroll
        for (int q = 0; q < 4; q++) {
            int idx = q * 256 + tid;
            int row = idx >> 3, seg = (idx & 7);
            int off = row * ROWB_G + seg * 16;
            int gi = m0 + row;
            uint4 ahi = zz, alo = zz;
            if (gi < M) {
                ahi = *(const uint4*)&g_ha_hi[gi * H1 + k0 + seg * 8];
                alo = *(const uint4*)&g_ha_lo[gi * H1 + k0 + seg * 8];
            }
            *(uint4*)(smem_raw + GA_HI + off) = ahi;
            *(uint4*)(smem_raw + GA_LO + off) = alo;
            *(uint4*)(smem_raw + GB_HI + off) = *(const uint4*)&g_w23t_hi[(n0 + row) * H1 + k0 + seg * 8];
            *(uint4*)(smem_raw + GB_LO + off) = *(const uint4*)&g_w23t_lo[(n0 + row) * H1 + k0 + seg * 8];
        }
        __syncthreads();
#pragma unroll
        for (int ks = 0; ks < 4; ks++) {
            uint32_t k2 = (uint32_t)(ks * 32);
            uint32_t Ahi[4][4], Bhi[4][2], Blo[4][2];
#pragma unroll
            for (int mf = 0; mf < 4; mf++)
                ldsm_x4(Ahi[mf], smb + GA_HI + aoffA + mf * (16 * ROWB_G) + k2);
#pragma unroll
            for (int nf = 0; nf < 4; nf++) {
                ldsm_x2(Bhi[nf], smb + GB_HI + aoffB + nf * (8 * ROWB_G) + k2);
                ldsm_x2(Blo[nf], smb + GB_LO + aoffB + nf * (8 * ROWB_G) + k2);
            }
#pragma unroll
            for (int mf = 0; mf < 4; mf++)
#pragma unroll
                for (int nf = 0; nf < 4; nf++) {
                    mma_bf16(acc[mf][nf], Ahi[mf], Bhi[nf]);
                    mma_bf16(acc[mf][nf], Ahi[mf], Blo[nf]);
                }
            uint32_t Alo[4][4];
#pragma unroll
            for (int mf = 0; mf < 4; mf++)
                ldsm_x4(Alo[mf], smb + GA_LO + aoffA + mf * (16 * ROWB_G) + k2);
#pragma unroll
            for (int mf = 0; mf < 4; mf++)
#pragma unroll
                for (int nf = 0; nf < 4; nf++)
                    mma_bf16(acc[mf][nf], Alo[mf], Bhi[nf]);
        }
    }
    int g = lane >> 2, q = lane & 3;
#pragma unroll
    for (int mf = 0; mf < 4; mf++)
#pragma unroll
        for (int rr = 0; rr < 2; rr++) {
            int i = m0 + warp_m * 64 + mf * 16 + g + rr * 8;
            if (i < M) {
#pragma unroll
                for (int nf = 0; nf < 4; nf++) {
                    int j = n0 + warp_n * 32 + nf * 8 + q * 2;
                    *(float2*)&g_y23[i * H1 + j] =
                        make_float2(acc[mf][nf][rr * 2], acc[mf][nf][rr * 2 + 1]);
                }
            }
        }
}

// ---------------- agg1: unroll-4 gather; h = relu(rs_in*sum + b1); emit (h*rs_out) bf16 ----------------
__global__ void agg1_kernel(const float* __restrict__ b1) {
    int d = blockIdx.x, t = threadIdx.x;
    int s = g_row_off[d], e = s + g_deg_in[d];
    const float2* Y = (const float2*)g_y1;
    float2 a0 = make_float2(0.f, 0.f), a1 = a0, a2 = a0, a3 = a0;
    int i = s;
    for (; i + 3 < e; i += 4) {
        int s0 = g_perm_src[i], s1 = g_perm_src[i + 1];
        int s2 = g_perm_src[i + 2], s3 = g_perm_src[i + 3];
        float2 v0 = Y[s0 * (H1 / 2) + t];
        float2 v1 = Y[s1 * (H1 / 2) + t];
        float2 v2 = Y[s2 * (H1 / 2) + t];
        float2 v3 = Y[s3 * (H1 / 2) + t];
        a0.x += v0.x; a0.y += v0.y;
        a1.x += v1.x; a1.y += v1.y;
        a2.x += v2.x; a2.y += v2.y;
        a3.x += v3.x; a3.y += v3.y;
    }
    for (; i < e; i++) {
        int sn = g_perm_src[i];
        float2 v = Y[sn * (H1 / 2) + t];
        a0.x += v.x; a0.y += v.y;
    }
    float ax = (a0.x + a1.x) + (a2.x + a3.x);
    float ay = (a0.y + a1.y) + (a2.y + a3.y);
    float ri = g_rs_in[d];
    float ro = g_rs_out[d];
    float h0 = fmaxf(ax * ri + b1[2 * t], 0.f) * ro;
    float h1 = fmaxf(ay * ri + b1[2 * t + 1], 0.f) * ro;
    __nv_bfloat16 hi0, lo0, hi1, lo1;
    bsplit(h0, hi0, lo0);
    bsplit(h1, hi1, lo1);
    ((uint32_t*)g_ha_hi)[d * (H1 / 2) + t] = pack_bf2(hi0, hi1);
    ((uint32_t*)g_ha_lo)[d * (H1 / 2) + t] = pack_bf2(lo0, lo1);
}

// ---------------- aggz: unroll-4 gather; z = (s0+b2) + noise*exp(s1+b3) ----------------
__global__ void aggz_kernel(const float* __restrict__ b2, const float* __restrict__ b3,
                            const float* __restrict__ noise) {
    __shared__ float sm[H1];
    int d = blockIdx.x, t = threadIdx.x;
    int s = g_row_off[d], e = s + g_deg_in[d];
    const float2* Y = (const float2*)g_y23;
    float2 a0 = make_float2(0.f, 0.f), a1 = a0, a2 = a0, a3 = a0;
    int i = s;
    for (; i + 3 < e; i += 4) {
        int s0 = g_perm_src[i], s1 = g_perm_src[i + 1];
        int s2 = g_perm_src[i + 2], s3 = g_perm_src[i + 3];
        float2 v0 = Y[s0 * (H1 / 2) + t];
        float2 v1 = Y[s1 * (H1 / 2) + t];
        float2 v2 = Y[s2 * (H1 / 2) + t];
        float2 v3 = Y[s3 * (H1 / 2) + t];
        a0.x += v0.x; a0.y += v0.y;
        a1.x += v1.x; a1.y += v1.y;
        a2.x += v2.x; a2.y += v2.y;
        a3.x += v3.x; a3.y += v3.y;
    }
    for (; i < e; i++) {
        int sn = g_perm_src[i];
        float2 v = Y[sn * (H1 / 2) + t];
        a0.x += v.x; a0.y += v.y;
    }
    float ax = (a0.x + a1.x) + (a2.x + a3.x);
    float ay = (a0.y + a1.y) + (a2.y + a3.y);
    float ri = g_rs_in[d];
    sm[2 * t] = ax * ri;
    sm[2 * t + 1] = ay * ri;
    __syncthreads();
    if (t < 64) {
#pragma unroll
        for (int q = 0; q < 2; q++) {
            int c = 2 * t + q;
            float mean = sm[c] + b2[c];
            float ls = sm[c + H2] + b3[c];
            float zv = mean + noise[d * H2 + c] * expf(ls);
            __nv_bfloat16 hi, lo;
            bsplit(zv, hi, lo);
            g_zhi[d * H2 + c] = hi;
            g_zlo[d * H2 + c] = lo;
        }
    }
}

// ---------------- final decoder: heterogeneous HMMA (65%) + FFMA2 (35%) ----------------
#define ROWB 272
#define IBUF (64 * ROWB)                 // 17408
#define JBUF (128 * ROWB)                // 34816
#define SM_HI_I 0
#define SM_LO_I (IBUF)
#define SM_HI_J (2 * IBUF)
#define SM_LO_J (2 * IBUF + JBUF)
#define SM_TOTAL (2 * IBUF + 2 * JBUF)   // 104448 -> 2 CTAs/SM

__global__ void __launch_bounds__(256, 2) final_kernel(float* __restrict__ out, int n,
                                                       int fullg, int fTail) {
    extern __shared__ char smem_raw[];
    int tid = threadIdx.x;
    int w = tid >> 5, lane = tid & 31;

    // ---- map blockIdx -> (class, pair p, half) with 7:13 interleave per 20 pairs ----
    int x = blockIdx.x;
    bool is_ffma;
    int p, half = 0;
    if (x < fullg * 33) {
        int gg = x / 33, s = x % 33;
        if (s < 7) { is_ffma = true; p = gg * 20 + s; }
        else { int hh = s - 7; is_ffma = false; p = gg * 20 + 7 + (hh >> 1); half = hh & 1; }
    } else {
        int xt = x - fullg * 33;
        if (xt < fTail) { is_ffma = true; p = fullg * 20 + xt; }
        else { int hh = xt - fTail; is_ffma = false; p = fullg * 20 + fTail + (hh >> 1); half = hh & 1; }
    }
    int bi = (int)((sqrtf(8.0f * (float)p + 1.0f) - 1.0f) * 0.5f);
    while ((bi + 1) * (bi + 2) / 2 <= p) bi++;
    while (bi * (bi + 1) / 2 > p) bi--;
    int bj = p - bi * (bi + 1) / 2;

    if (is_ffma) {
        // ================= FFMA2 path: full 128x128 tile =================
        int i0 = bi * 128, j0 = bj * 128;
        float* smf = (float*)smem_raw;
        const int AS = 0, BS = 32 * 132;       // two [32 k][132 row] fp32 buffers
        int tx = tid & 15, ty = tid >> 4;
        unsigned long long acc[8][4] = {};

        for (int k0 = 0; k0 < H2; k0 += 32) {
            __syncthreads();
            for (int it = tid; it < 512; it += 256) {
                int row = it >> 2, seg = it & 3;
                int kk = k0 + seg * 8;
                int gi = i0 + row, gj = j0 + row;
                float zi[8], zj[8];
                if (gi < n) {
                    uint4 h = *(const uint4*)&g_zhi[gi * H2 + kk];
                    uint4 l = *(const uint4*)&g_zlo[gi * H2 + kk];
                    bf2x_to_f2(h.x, l.x, zi[0], zi[1]); bf2x_to_f2(h.y, l.y, zi[2], zi[3]);
                    bf2x_to_f2(h.z, l.z, zi[4], zi[5]); bf2x_to_f2(h.w, l.w, zi[6], zi[7]);
                } else {
#pragma unroll
                    for (int u = 0; u < 8; u++) zi[u] = 0.f;
                }
                if (gj < n) {
                    uint4 h = *(const uint4*)&g_zhi[gj * H2 + kk];
                    uint4 l = *(const uint4*)&g_zlo[gj * H2 + kk];
                    bf2x_to_f2(h.x, l.x, zj[0], zj[1]); bf2x_to_f2(h.y, l.y, zj[2], zj[3]);
                    bf2x_to_f2(h.z, l.z, zj[4], zj[5]); bf2x_to_f2(h.w, l.w, zj[6], zj[7]);
                } else {
#pragma unroll
                    for (int u = 0; u < 8; u++) zj[u] = 0.f;
                }
#pragma unroll
                for (int u = 0; u < 8; u++) {
                    smf[AS + (seg * 8 + u) * 132 + row] = zi[u];
                    smf[BS + (seg * 8 + u) * 132 + row] = zj[u];
                }
            }
            __syncthreads();
#pragma unroll 4
            for (int k = 0; k < 32; k++) {
                float4 al = *(const float4*)&smf[AS + k * 132 + ty * 4];
                float4 ah = *(const float4*)&smf[AS + k * 132 + 64 + ty * 4];
                float4 bl = *(const float4*)&smf[BS + k * 132 + tx * 4];
                float4 bh = *(const float4*)&smf[BS + k * 132 + 64 + tx * 4];
                unsigned long long b0 = pack2f(bl.x, bl.y), b1v = pack2f(bl.z, bl.w);
                unsigned long long b2v = pack2f(bh.x, bh.y), b3v = pack2f(bh.z, bh.w);
                float av[8] = {al.x, al.y, al.z, al.w, ah.x, ah.y, ah.z, ah.w};
#pragma unroll
                for (int r = 0; r < 8; r++) {
                    unsigned long long a = pack_dup(av[r]);
                    ffma2(acc[r][0], a, b0);
                    ffma2(acc[r][1], a, b1v);
                    ffma2(acc[r][2], a, b2v);
                    ffma2(acc[r][3], a, b3v);
                }
            }
        }

        float2 sg[8][4];
#pragma unroll
        for (int r = 0; r < 8; r++)
#pragma unroll
            for (int q = 0; q < 4; q++) {
                float2 v = unpack2f(acc[r][q]);
                sg[r][q] = make_float2(sigm(v.x), sigm(v.y));
            }

        // direct store: out[i][j]
#pragma unroll
        for (int r = 0; r < 8; r++) {
            int i = i0 + ((r < 4) ? (ty * 4 + r) : (64 + ty * 4 + r - 4));
            if (i < n) {
#pragma unroll
                for (int q = 0; q < 4; q++) {
                    int j = j0 + ((q < 2) ? (tx * 4 + 2 * q) : (64 + tx * 4 + 2 * (q - 2)));
                    size_t off = (size_t)i * n + j;
                    if (j + 1 < n) {
                        *(float2*)&out[off] = sg[r][q];
                    } else if (j < n) {
                        out[off] = sg[r][q].x;
                    }
                }
            }
        }

        // mirror store via smem transpose: smt[128 j][132 i] fp32 = 67584B
        if (bi != bj) {
            __syncthreads();
            float* smt = (float*)smem_raw;
#pragma unroll
            for (int r = 0; r < 8; r++) {
                int irel = (r < 4) ? (ty * 4 + r) : (64 + ty * 4 + r - 4);
#pragma unroll
                for (int q = 0; q < 4; q++) {
                    int jrel = (q < 2) ? (tx * 4 + 2 * q) : (64 + tx * 4 + 2 * (q - 2));
                    smt[(jrel)     * 132 + irel] = sg[r][q].x;
                    smt[(jrel + 1) * 132 + irel] = sg[r][q].y;
                }
            }
            __syncthreads();
            for (int c = tid; c < 128 * 32; c += 256) {
                int jr = c >> 5;
                int i4 = (c & 31) * 4;
                int gi = i0 + i4;
                size_t off = (size_t)(j0 + jr) * n + gi;
                float4 v = *(const float4*)&smt[jr * 132 + i4];
                if (gi + 3 < n) {
                    *(float4*)&out[off] = v;
                } else {
                    float a[4] = {v.x, v.y, v.z, v.w};
#pragma unroll
                    for (int u = 0; u < 4; u++)
                        if (gi + u < n) out[off + u] = a[u];
                }
            }
        }
        return;
    }

    // ================= HMMA path: 64x128 half-tile =================
    int i0 = bi * 128 + half * 64;
    int j0 = bj * 128;

    const uint4 zz = make_uint4(0u, 0u, 0u, 0u);
    for (int c = tid; c < 2048; c += 256) {
        int row = c >> 4, seg = c & 15;
        int off = row * ROWB + seg * 16;
        int gj = j0 + row;
        uint4 hi_j = zz, lo_j = zz;
        if (gj < n) {
            hi_j = *(const uint4*)&g_zhi[gj * H2 + seg * 8];
            lo_j = *(const uint4*)&g_zlo[gj * H2 + seg * 8];
        }
        *(uint4*)(smem_raw + SM_HI_J + off) = hi_j;
        *(uint4*)(smem_raw + SM_LO_J + off) = lo_j;
        if (row < 64) {
            int gi = i0 + row;
            uint4 hi_i = zz, lo_i = zz;
            if (gi < n) {
                hi_i = *(const uint4*)&g_zhi[gi * H2 + seg * 8];
                lo_i = *(const uint4*)&g_zlo[gi * H2 + seg * 8];
            }
            *(uint4*)(smem_raw + SM_HI_I + off) = hi_i;
            *(uint4*)(smem_raw + SM_LO_I + off) = lo_i;
        }
    }
    __syncthreads();

    uint32_t smb = smem_u32(smem_raw);
    int warp_m = w & 1, warp_n = w >> 1;      // 2 x 4 warp grid; warp tile 32m x 32n
    uint32_t aoffA = (uint32_t)((warp_m * 32 + (lane & 15)) * ROWB + (lane >> 4) * 16);
    uint32_t aoffB = (uint32_t)((warp_n * 32 + (lane & 7)) * ROWB + ((lane >> 3) & 1) * 16);

    float acc[2][4][4] = {};

    for (int ks = 0; ks < 8; ks++) {
        uint32_t k2 = (uint32_t)(ks * 32);
        uint32_t Ahi[2][4], Bhi[4][2], Blo[4][2];
#pragma unroll
        for (int mf = 0; mf < 2; mf++)
            ldsm_x4(Ahi[mf], smb + SM_HI_I + aoffA + mf * (16 * ROWB) + k2);
#pragma unroll
        for (int nf = 0; nf < 4; nf++) {
            ldsm_x2(Bhi[nf], smb + SM_HI_J + aoffB + nf * (8 * ROWB) + k2);
            ldsm_x2(Blo[nf], smb + SM_LO_J + aoffB + nf * (8 * ROWB) + k2);
        }
#pragma unroll
        for (int mf = 0; mf < 2; mf++)
#pragma unroll
            for (int nf = 0; nf < 4; nf++) {
                mma_bf16(acc[mf][nf], Ahi[mf], Bhi[nf]);
                mma_bf16(acc[mf][nf], Ahi[mf], Blo[nf]);
            }
        uint32_t Alo[2][4];
#pragma unroll
        for (int mf = 0; mf < 2; mf++)
            ldsm_x4(Alo[mf], smb + SM_LO_I + aoffA + mf * (16 * ROWB) + k2);
#pragma unroll
        for (int mf = 0; mf < 2; mf++)
#pragma unroll
            for (int nf = 0; nf < 4; nf++)
                mma_bf16(acc[mf][nf], Alo[mf], Bhi[nf]);
    }

#pragma unroll
    for (int mf = 0; mf < 2; mf++)
#pragma unroll
        for (int nf = 0; nf < 4; nf++)
#pragma unroll
            for (int r = 0; r < 4; r++)
                acc[mf][nf][r] = sigm(acc[mf][nf][r]);

    int g = lane >> 2, q = lane & 3;

#pragma unroll
    for (int mf = 0; mf < 2; mf++) {
#pragma unroll
        for (int rr = 0; rr < 2; rr++) {
            int i = i0 + warp_m * 32 + mf * 16 + g + rr * 8;
            if (i < n) {
#pragma unroll
                for (int nf = 0; nf < 4; nf++) {
                    int j = j0 + warp_n * 32 + nf * 8 + q * 2;
                    if (j + 1 < n) {
                        *(float2*)&out[(size_t)i * n + j] =
                            make_float2(acc[mf][nf][rr * 2], acc[mf][nf][rr * 2 + 1]);
                    } else if (j < n) {
                        out[(size_t)i * n + j] = acc[mf][nf][rr * 2];
                    }
                }
            }
        }
    }

    if (bi != bj) {
        __syncthreads();
        float* smt = (float*)smem_raw;
#pragma unroll
        for (int mf = 0; mf < 2; mf++) {
            int irel_base = warp_m * 32 + mf * 16 + g;
#pragma unroll
            for (int nf = 0; nf < 4; nf++) {
                int jrel = warp_n * 32 + nf * 8 + q * 2;
                smt[(jrel)     * 68 + irel_base]     = acc[mf][nf][0];
                smt[(jrel + 1) * 68 + irel_base]     = acc[mf][nf][1];
                smt[(jrel)     * 68 + irel_base + 8] = acc[mf][nf][2];
                smt[(jrel + 1) * 68 + irel_base + 8] = acc[mf][nf][3];
            }
        }
        __syncthreads();
        for (int c = tid; c < 128 * 16; c += 256) {
            int jr = c >> 4;
            int i4 = (c & 15) * 4;
            int gi = i0 + i4;
            size_t off = (size_t)(j0 + jr) * n + gi;
            float4 v = *(const float4*)&smt[jr * 68 + i4];
            if (gi + 3 < n) {
                *(float4*)&out[off] = v;
            } else {
                float a[4] = {v.x, v.y, v.z, v.w};
#pragma unroll
                for (int u = 0; u < 4; u++)
                    if (gi + u < n) out[off + u] = a[u];
            }
        }
    }
}

// ---------------- launch ----------------
extern "C" void kernel_launch(void* const* d_in, const int* in_sizes, int n_in,
                              void* d_out, int out_size) {
    const float* features = (const float*)d_in[0];
    const int*   src      = (const int*)d_in[1];
    const int*   dst      = (const int*)d_in[2];
    const float* noise    = (const float*)d_in[3];
    const float* W1       = (const float*)d_in[4];
    const float* b1       = (const float*)d_in[5];
    const float* W2       = (const float*)d_in[6];
    const float* b2       = (const float*)d_in[7];
    const float* W3       = (const float*)d_in[8];
    const float* b3       = (const float*)d_in[9];
    int N = in_sizes[0] / IN_DIM;
    int E = in_sizes[1];
    float* out = (float*)d_out;

    cudaFuncSetAttribute(final_kernel, cudaFuncAttributeMaxDynamicSharedMemorySize, SM_TOTAL);
    cudaFuncSetAttribute(gemm1_hmma, cudaFuncAttributeMaxDynamicSharedMemorySize, G_TOTAL);
    cudaFuncSetAttribute(gemm23_hmma, cudaFuncAttributeMaxDynamicSharedMemorySize, G_TOTAL);

    zero_kernel<<<(N + 255) / 256, 256>>>(N);
    degree_kernel<<<(E + 255) / 256, 256>>>(src, dst, E);
    rs_alloc_kernel<<<(N + 255) / 256, 256>>>(N);
    perm_kernel<<<(E + 255) / 256, 256>>>(src, dst, E);
    convw_kernel<<<(H1 * IN_DIM + H1 * H1 + 255) / 256, 256>>>(W1, W2, W3);

    dim3 gg((N + 127) / 128, 2);
    gemm1_hmma<<<gg, 256, G_TOTAL>>>(features, N);
    agg1_kernel<<<N, 128>>>(b1);
    gemm23_hmma<<<gg, 256, G_TOTAL>>>(N);
    aggz_kernel<<<N, 128>>>(b2, b3, noise);

    int T = (N + 127) / 128;
    int P = T * (T + 1) / 2;
    int fullg = P / 20, rem = P % 20;
    int fTail = rem < 7 ? rem : 7;
    int hTail = rem - fTail;
    int grid = fullg * 33 + fTail + 2 * hTail;
    final_kernel<<<grid, 256, SM_TOTAL>>>(out, N, fullg, fTail);
}

// round 14
// speedup vs baseline: 1.1715x; 1.1715x over previous
#include <cuda_runtime.h>
#include <cuda_bf16.h>
#include <cstdint>

#define MAXN 10000
#define MAXE 320000
#define IN_DIM 512
#define H1 256
#define H2 128

// ---------------- scratch (device globals; no allocation allowed) ----------------
__device__ int   g_deg_out[MAXN];
__device__ int   g_deg_in[MAXN];
__device__ int   g_cnt[MAXN];
__device__ int   g_alloc;
__device__ float g_rs_out[MAXN];
__device__ float g_rs_in[MAXN];
__device__ int   g_row_off[MAXN];
__device__ int   g_perm_src[MAXE];
__device__ float g_y1[MAXN * H1];    // (x*rs_out) @ W1
__device__ float g_y23[MAXN * H1];   // (h*rs_out) @ [W2|W3]
__device__ __align__(16) __nv_bfloat16 g_ha_hi[MAXN * H1];  // (h*rs_out) bf16 hi
__device__ __align__(16) __nv_bfloat16 g_ha_lo[MAXN * H1];  // (h*rs_out) bf16 lo
__device__ __align__(16) __nv_bfloat16 g_w1t_hi[H1 * IN_DIM];   // W1^T [256][512]
__device__ __align__(16) __nv_bfloat16 g_w1t_lo[H1 * IN_DIM];
__device__ __align__(16) __nv_bfloat16 g_w23t_hi[H1 * H1];      // [W2|W3]^T [256][256]
__device__ __align__(16) __nv_bfloat16 g_w23t_lo[H1 * H1];
__device__ __align__(16) __nv_bfloat16 g_zhi[MAXN * H2];
__device__ __align__(16) __nv_bfloat16 g_zlo[MAXN * H2];

// ---------------- helpers ----------------
__device__ __forceinline__ float sigm(float x) {
    return 1.0f / (1.0f + __expf(-x));
}
__device__ __forceinline__ void bsplit(float v, __nv_bfloat16& hi, __nv_bfloat16& lo) {
    hi = __float2bfloat16(v);
    lo = __float2bfloat16(v - __bfloat162float(hi));
}
__device__ __forceinline__ uint32_t smem_u32(const void* p) {
    uint32_t a;
    asm("{ .reg .u64 t; cvta.to.shared.u64 t, %1; cvt.u32.u64 %0, t; }" : "=r"(a) : "l"(p));
    return a;
}
__device__ __forceinline__ void ldsm_x4(uint32_t a[4], uint32_t addr) {
    asm volatile("ldmatrix.sync.aligned.m8n8.x4.shared.b16 {%0,%1,%2,%3}, [%4];"
        : "=r"(a[0]), "=r"(a[1]), "=r"(a[2]), "=r"(a[3]) : "r"(addr));
}
__device__ __forceinline__ void ldsm_x2(uint32_t b[2], uint32_t addr) {
    asm volatile("ldmatrix.sync.aligned.m8n8.x2.shared.b16 {%0,%1}, [%2];"
        : "=r"(b[0]), "=r"(b[1]) : "r"(addr));
}
__device__ __forceinline__ void mma_bf16(float d[4], const uint32_t a[4], const uint32_t b[2]) {
    asm volatile("mma.sync.aligned.m16n8k16.row.col.f32.bf16.bf16.f32 "
        "{%0,%1,%2,%3}, {%4,%5,%6,%7}, {%8,%9}, {%0,%1,%2,%3};"
        : "+f"(d[0]), "+f"(d[1]), "+f"(d[2]), "+f"(d[3])
        : "r"(a[0]), "r"(a[1]), "r"(a[2]), "r"(a[3]), "r"(b[0]), "r"(b[1]));
}
__device__ __forceinline__ uint32_t pack_bf2(__nv_bfloat16 a, __nv_bfloat16 b) {
    __nv_bfloat162 v(a, b);
    return *(uint32_t*)&v;
}

// ---------------- small setup kernels ----------------
__global__ void zero_kernel(int n) {
    int i = blockIdx.x * blockDim.x + threadIdx.x;
    if (i < n) { g_deg_out[i] = 0; g_deg_in[i] = 0; g_cnt[i] = 0; }
    if (i == 0) g_alloc = 0;
}

__global__ void degree_kernel(const int* __restrict__ src, const int* __restrict__ dst, int e) {
    int i = blockIdx.x * blockDim.x + threadIdx.x;
    if (i < e) {
        atomicAdd(&g_deg_out[src[i]], 1);
        atomicAdd(&g_deg_in[dst[i]], 1);
    }
}

__global__ void rs_alloc_kernel(int n) {
    int i = blockIdx.x * blockDim.x + threadIdx.x;
    if (i < n) {
        int dIn = g_deg_in[i];
        g_rs_out[i] = rsqrtf(fmaxf((float)g_deg_out[i], 1.0f));
        g_rs_in[i]  = rsqrtf(fmaxf((float)dIn, 1.0f));
        g_row_off[i] = atomicAdd(&g_alloc, dIn);
    }
}

__global__ void perm_kernel(const int* __restrict__ src, const int* __restrict__ dst, int e) {
    int i = blockIdx.x * blockDim.x + threadIdx.x;
    if (i < e) {
        int d = dst[i];
        int pos = atomicAdd(&g_cnt[d], 1);
        g_perm_src[g_row_off[d] + pos] = src[i];
    }
}

// one-shot weight transpose + bf16 hi/lo split
__global__ void convw_kernel(const float* __restrict__ W1, const float* __restrict__ W2,
                             const float* __restrict__ W3) {
    int idx = blockIdx.x * blockDim.x + threadIdx.x;
    if (idx < H1 * IN_DIM) {
        int nn = idx >> 9, k = idx & 511;
        __nv_bfloat16 hi, lo;
        bsplit(W1[k * H1 + nn], hi, lo);
        g_w1t_hi[idx] = hi;
        g_w1t_lo[idx] = lo;
    } else {
        int j = idx - H1 * IN_DIM;
        if (j < H1 * H1) {
            int nn = j >> 8, k = j & 255;
            float v = (nn < H2) ? W2[k * H2 + nn] : W3[k * H2 + (nn - H2)];
            __nv_bfloat16 hi, lo;
            bsplit(v, hi, lo);
            g_w23t_hi[j] = hi;
            g_w23t_lo[j] = lo;
        }
    }
}

// ---------------- HMMA GEMM smem geometry ----------------
#define ROWB_G 144
#define GBUF (128 * ROWB_G)
#define GA_HI 0
#define GA_LO GBUF
#define GB_HI (2 * GBUF)
#define GB_LO (3 * GBUF)
#define G_TOTAL (4 * GBUF)             // 73728

// ---------------- GEMM1: y1 = (X*rs_out) @ W1 ----------------
__global__ void __launch_bounds__(256) gemm1_hmma(const float* __restrict__ X, int M) {
    extern __shared__ char smem_raw[];
    int tid = threadIdx.x;
    int w = tid >> 5, lane = tid & 31;
    int m0 = blockIdx.x * 128, n0 = blockIdx.y * 128;
    uint32_t smb = smem_u32(smem_raw);
    int warp_m = w & 1, warp_n = w >> 1;
    uint32_t aoffA = (uint32_t)((warp_m * 64 + (lane & 15)) * ROWB_G + (lane >> 4) * 16);
    uint32_t aoffB = (uint32_t)((warp_n * 32 + (lane & 7)) * ROWB_G + ((lane >> 3) & 1) * 16);

    float acc[4][4][4] = {};

    for (int ch = 0; ch < IN_DIM / 64; ch++) {
        int k0 = ch * 64;
        __syncthreads();
#pragma unroll
        for (int q = 0; q < 8; q++) {
            int idx = q * 256 + tid;
            int row = idx >> 4, c4 = (idx & 15) * 4;
            int gi = m0 + row;
            float4 v = make_float4(0.f, 0.f, 0.f, 0.f);
            float ro = 0.f;
            if (gi < M) { v = *(const float4*)&X[gi * IN_DIM + k0 + c4]; ro = g_rs_out[gi]; }
            __nv_bfloat16 h0, l0, h1, l1, h2, l2, h3, l3;
            bsplit(v.x * ro, h0, l0); bsplit(v.y * ro, h1, l1);
            bsplit(v.z * ro, h2, l2); bsplit(v.w * ro, h3, l3);
            int off = row * ROWB_G + c4 * 2;
            *(uint2*)(smem_raw + GA_HI + off) = make_uint2(pack_bf2(h0, h1), pack_bf2(h2, h3));
            *(uint2*)(smem_raw + GA_LO + off) = make_uint2(pack_bf2(l0, l1), pack_bf2(l2, l3));
        }
#pragma unroll
        for (int q = 0; q < 4; q++) {
            int idx = q * 256 + tid;
            int row = idx >> 3, seg = (idx & 7);
            int off = row * ROWB_G + seg * 16;
            *(uint4*)(smem_raw + GB_HI + off) = *(const uint4*)&g_w1t_hi[(n0 + row) * IN_DIM + k0 + seg * 8];
            *(uint4*)(smem_raw + GB_LO + off) = *(const uint4*)&g_w1t_lo[(n0 + row) * IN_DIM + k0 + seg * 8];
        }
        __syncthreads();
#pragma unroll
        for (int ks = 0; ks < 4; ks++) {
            uint32_t k2 = (uint32_t)(ks * 32);
            uint32_t Ahi[4][4], Bhi[4][2], Blo[4][2];
#pragma unroll
            for (int mf = 0; mf < 4; mf++)
                ldsm_x4(Ahi[mf], smb + GA_HI + aoffA + mf * (16 * ROWB_G) + k2);
#pragma unroll
            for (int nf = 0; nf < 4; nf++) {
                ldsm_x2(Bhi[nf], smb + GB_HI + aoffB + nf * (8 * ROWB_G) + k2);
                ldsm_x2(Blo[nf], smb + GB_LO + aoffB + nf * (8 * ROWB_G) + k2);
            }
#pragma unroll
            for (int mf = 0; mf < 4; mf++)
#pragma unroll
                for (int nf = 0; nf < 4; nf++) {
                    mma_bf16(acc[mf][nf], Ahi[mf], Bhi[nf]);
                    mma_bf16(acc[mf][nf], Ahi[mf], Blo[nf]);
                }
            uint32_t Alo[4][4];
#pragma unroll
            for (int mf = 0; mf < 4; mf++)
                ldsm_x4(Alo[mf], smb + GA_LO + aoffA + mf * (16 * ROWB_G) + k2);
#pragma unroll
            for (int mf = 0; mf < 4; mf++)
#pragma unroll
                for (int nf = 0; nf < 4; nf++)
                    mma_bf16(acc[mf][nf], Alo[mf], Bhi[nf]);
        }
    }
    int g = lane >> 2, q = lane & 3;
#pragma unroll
    for (int mf = 0; mf < 4; mf++)
#pragma unroll
        for (int rr = 0; rr < 2; rr++) {
            int i = m0 + warp_m * 64 + mf * 16 + g + rr * 8;
            if (i < M) {
#pragma unroll
                for (int nf = 0; nf < 4; nf++) {
                    int j = n0 + warp_n * 32 + nf * 8 + q * 2;
                    *(float2*)&g_y1[i * H1 + j] =
                        make_float2(acc[mf][nf][rr * 2], acc[mf][nf][rr * 2 + 1]);
                }
            }
        }
}

// ---------------- GEMM23: y23 = (h*rs_out) @ [W2|W3] ----------------
__global__ void __launch_bounds__(256) gemm23_hmma(int M) {
    extern __shared__ char smem_raw[];
    int tid = threadIdx.x;
    int w = tid >> 5, lane = tid & 31;
    int m0 = blockIdx.x * 128, n0 = blockIdx.y * 128;
    uint32_t smb = smem_u32(smem_raw);
    int warp_m = w & 1, warp_n = w >> 1;
    uint32_t aoffA = (uint32_t)((warp_m * 64 + (lane & 15)) * ROWB_G + (lane >> 4) * 16);
    uint32_t aoffB = (uint32_t)((warp_n * 32 + (lane & 7)) * ROWB_G + ((lane >> 3) & 1) * 16);

    float acc[4][4][4] = {};
    const uint4 zz = make_uint4(0u, 0u, 0u, 0u);

    for (int ch = 0; ch < H1 / 64; ch++) {
        int k0 = ch * 64;
        __syncthreads();
#pragma unroll
        for (int q = 0; q < 4; q++) {
            int idx = q * 256 + tid;
            int row = idx >> 3, seg = (idx & 7);
            int off = row * ROWB_G + seg * 16;
            int gi = m0 + row;
            uint4 ahi = zz, alo = zz;
            if (gi < M) {
                ahi = *(const uint4*)&g_ha_hi[gi * H1 + k0 + seg * 8];
                alo = *(const uint4*)&g_ha_lo[gi * H1 + k0 + seg * 8];
            }
            *(uint4*)(smem_raw + GA_HI + off) = ahi;
            *(uint4*)(smem_raw + GA_LO + off) = alo;
            *(uint4*)(smem_raw + GB_HI + off) = *(const uint4*)&g_w23t_hi[(n0 + row) * H1 + k0 + seg * 8];
            *(uint4*)(smem_raw + GB_LO + off) = *(const uint4*)&g_w23t_lo[(n0 + row) * H1 + k0 + seg * 8];
        }
        __syncthreads();
#pragma unroll
        for (int ks = 0; ks < 4; ks++) {
            uint32_t k2 = (uint32_t)(ks * 32);
            uint32_t Ahi[4][4], Bhi[4][2], Blo[4][2];
#pragma unroll
            for (int mf = 0; mf < 4; mf++)
                ldsm_x4(Ahi[mf], smb + GA_HI + aoffA + mf * (16 * ROWB_G) + k2);
#pragma unroll
            for (int nf = 0; nf < 4; nf++) {
                ldsm_x2(Bhi[nf], smb + GB_HI + aoffB + nf * (8 * ROWB_G) + k2);
                ldsm_x2(Blo[nf], smb + GB_LO + aoffB + nf * (8 * ROWB_G) + k2);
            }
#pragma unroll
            for (int mf = 0; mf < 4; mf++)
#pragma unroll
                for (int nf = 0; nf < 4; nf++) {
                    mma_bf16(acc[mf][nf], Ahi[mf], Bhi[nf]);
                    mma_bf16(acc[mf][nf], Ahi[mf], Blo[nf]);
                }
            uint32_t Alo[4][4];
#pragma unroll
            for (int mf = 0; mf < 4; mf++)
                ldsm_x4(Alo[mf], smb + GA_LO + aoffA + mf * (16 * ROWB_G) + k2);
#pragma unroll
            for (int mf = 0; mf < 4; mf++)
#pragma unroll
                for (int nf = 0; nf < 4; nf++)
                    mma_bf16(acc[mf][nf], Alo[mf], Bhi[nf]);
        }
    }
    int g = lane >> 2, q = lane & 3;
#pragma unroll
    for (int mf = 0; mf < 4; mf++)
#pragma unroll
        for (int rr = 0; rr < 2; rr++) {
            int i = m0 + warp_m * 64 + mf * 16 + g + rr * 8;
            if (i < M) {
#pragma unroll
                for (int nf = 0; nf < 4; nf++) {
                    int j = n0 + warp_n * 32 + nf * 8 + q * 2;
                    *(float2*)&g_y23[i * H1 + j] =
                        make_float2(acc[mf][nf][rr * 2], acc[mf][nf][rr * 2 + 1]);
                }
            }
        }
}

// ---------------- agg1: 256 thr, 1 col/thread, unroll-8 gather ----------------
__global__ void agg1_kernel(const float* __restrict__ b1) {
    int d = blockIdx.x, t = threadIdx.x;   // 256 threads, col t
    int s = g_row_off[d], e = s + g_deg_in[d];
    const float* Y = g_y1;
    float a0 = 0.f, a1 = 0.f, a2 = 0.f, a3 = 0.f;
    float a4 = 0.f, a5 = 0.f, a6 = 0.f, a7 = 0.f;
    int i = s;
    for (; i + 7 < e; i += 8) {
        int s0 = g_perm_src[i],     s1 = g_perm_src[i + 1];
        int s2 = g_perm_src[i + 2], s3 = g_perm_src[i + 3];
        int s4 = g_perm_src[i + 4], s5 = g_perm_src[i + 5];
        int s6 = g_perm_src[i + 6], s7 = g_perm_src[i + 7];
        a0 += Y[s0 * H1 + t]; a1 += Y[s1 * H1 + t];
        a2 += Y[s2 * H1 + t]; a3 += Y[s3 * H1 + t];
        a4 += Y[s4 * H1 + t]; a5 += Y[s5 * H1 + t];
        a6 += Y[s6 * H1 + t]; a7 += Y[s7 * H1 + t];
    }
    for (; i < e; i++) a0 += Y[g_perm_src[i] * H1 + t];
    float ax = ((a0 + a1) + (a2 + a3)) + ((a4 + a5) + (a6 + a7));
    float ri = g_rs_in[d];
    float ro = g_rs_out[d];
    float h0 = fmaxf(ax * ri + b1[t], 0.f) * ro;
    __nv_bfloat16 hi, lo;
    bsplit(h0, hi, lo);
    g_ha_hi[d * H1 + t] = hi;
    g_ha_lo[d * H1 + t] = lo;
}

// ---------------- aggz: 256 thr, 1 col/thread, unroll-8 gather ----------------
__global__ void aggz_kernel(const float* __restrict__ b2, const float* __restrict__ b3,
                            const float* __restrict__ noise) {
    __shared__ float sm[H1];
    int d = blockIdx.x, t = threadIdx.x;   // 256 threads
    int s = g_row_off[d], e = s + g_deg_in[d];
    const float* Y = g_y23;
    float a0 = 0.f, a1 = 0.f, a2 = 0.f, a3 = 0.f;
    float a4 = 0.f, a5 = 0.f, a6 = 0.f, a7 = 0.f;
    int i = s;
    for (; i + 7 < e; i += 8) {
        int s0 = g_perm_src[i],     s1 = g_perm_src[i + 1];
        int s2 = g_perm_src[i + 2], s3 = g_perm_src[i + 3];
        int s4 = g_perm_src[i + 4], s5 = g_perm_src[i + 5];
        int s6 = g_perm_src[i + 6], s7 = g_perm_src[i + 7];
        a0 += Y[s0 * H1 + t]; a1 += Y[s1 * H1 + t];
        a2 += Y[s2 * H1 + t]; a3 += Y[s3 * H1 + t];
        a4 += Y[s4 * H1 + t]; a5 += Y[s5 * H1 + t];
        a6 += Y[s6 * H1 + t]; a7 += Y[s7 * H1 + t];
    }
    for (; i < e; i++) a0 += Y[g_perm_src[i] * H1 + t];
    float ax = ((a0 + a1) + (a2 + a3)) + ((a4 + a5) + (a6 + a7));
    float ri = g_rs_in[d];
    sm[t] = ax * ri;
    __syncthreads();
    if (t < H2) {
        float mean = sm[t] + b2[t];
        float ls = sm[t + H2] + b3[t];
        float zv = mean + noise[d * H2 + t] * expf(ls);
        __nv_bfloat16 hi, lo;
        bsplit(zv, hi, lo);
        g_zhi[d * H2 + t] = hi;
        g_zlo[d * H2 + t] = lo;
    }
}

// ---------------- final decoder: mma.sync bf16 hi/lo, 64x128 half-tiles, 2 CTA/SM ----------------
#define ROWB 272
#define IBUF (64 * ROWB)                 // 17408
#define JBUF (128 * ROWB)                // 34816
#define SM_HI_I 0
#define SM_LO_I (IBUF)
#define SM_HI_J (2 * IBUF)
#define SM_LO_J (2 * IBUF + JBUF)
#define SM_TOTAL (2 * IBUF + 2 * JBUF)   // 104448 -> 2 CTAs/SM

__global__ void __launch_bounds__(256) final_kernel(float* __restrict__ out, int n) {
    extern __shared__ char smem_raw[];
    int tid = threadIdx.x;
    int w = tid >> 5, lane = tid & 31;

    int x = blockIdx.x;
    int p = x >> 1, half = x & 1;
    int bi = (int)((sqrtf(8.0f * (float)p + 1.0f) - 1.0f) * 0.5f);
    while ((bi + 1) * (bi + 2) / 2 <= p) bi++;
    while (bi * (bi + 1) / 2 > p) bi--;
    int bj = p - bi * (bi + 1) / 2;
    int i0 = bi * 128 + half * 64;       // 64-row i half-tile
    int j0 = bj * 128;                   // 128-col j tile

    // ---- load tiles: j 128 rows, i 64 rows ----
    const uint4 zz = make_uint4(0u, 0u, 0u, 0u);
    for (int c = tid; c < 2048; c += 256) {
        int row = c >> 4, seg = c & 15;
        int off = row * ROWB + seg * 16;
        int gj = j0 + row;
        uint4 hi_j = zz, lo_j = zz;
        if (gj < n) {
            hi_j = *(const uint4*)&g_zhi[gj * H2 + seg * 8];
            lo_j = *(const uint4*)&g_zlo[gj * H2 + seg * 8];
        }
        *(uint4*)(smem_raw + SM_HI_J + off) = hi_j;
        *(uint4*)(smem_raw + SM_LO_J + off) = lo_j;
        if (row < 64) {
            int gi = i0 + row;
            uint4 hi_i = zz, lo_i = zz;
            if (gi < n) {
                hi_i = *(const uint4*)&g_zhi[gi * H2 + seg * 8];
                lo_i = *(const uint4*)&g_zlo[gi * H2 + seg * 8];
            }
            *(uint4*)(smem_raw + SM_HI_I + off) = hi_i;
            *(uint4*)(smem_raw + SM_LO_I + off) = lo_i;
        }
    }
    __syncthreads();

    uint32_t smb = smem_u32(smem_raw);
    int warp_m = w & 1, warp_n = w >> 1;      // 2 x 4 warp grid; warp tile 32m x 32n
    uint32_t aoffA = (uint32_t)((warp_m * 32 + (lane & 15)) * ROWB + (lane >> 4) * 16);
    uint32_t aoffB = (uint32_t)((warp_n * 32 + (lane & 7)) * ROWB + ((lane >> 3) & 1) * 16);

    float acc[2][4][4] = {};

    for (int ks = 0; ks < 8; ks++) {
        uint32_t k2 = (uint32_t)(ks * 32);
        uint32_t Ahi[2][4], Bhi[4][2], Blo[4][2];
#pragma unroll
        for (int mf = 0; mf < 2; mf++)
            ldsm_x4(Ahi[mf], smb + SM_HI_I + aoffA + mf * (16 * ROWB) + k2);
#pragma unroll
        for (int nf = 0; nf < 4; nf++) {
            ldsm_x2(Bhi[nf], smb + SM_HI_J + aoffB + nf * (8 * ROWB) + k2);
            ldsm_x2(Blo[nf], smb + SM_LO_J + aoffB + nf * (8 * ROWB) + k2);
        }
#pragma unroll
        for (int mf = 0; mf < 2; mf++)
#pragma unroll
            for (int nf = 0; nf < 4; nf++) {
                mma_bf16(acc[mf][nf], Ahi[mf], Bhi[nf]);
                mma_bf16(acc[mf][nf], Ahi[mf], Blo[nf]);
            }
        uint32_t Alo[2][4];
#pragma unroll
        for (int mf = 0; mf < 2; mf++)
            ldsm_x4(Alo[mf], smb + SM_LO_I + aoffA + mf * (16 * ROWB) + k2);
#pragma unroll
        for (int mf = 0; mf < 2; mf++)
#pragma unroll
            for (int nf = 0; nf < 4; nf++)
                mma_bf16(acc[mf][nf], Alo[mf], Bhi[nf]);
    }

#pragma unroll
    for (int mf = 0; mf < 2; mf++)
#pragma unroll
        for (int nf = 0; nf < 4; nf++)
#pragma unroll
            for (int r = 0; r < 4; r++)
                acc[mf][nf][r] = sigm(acc[mf][nf][r]);

    int g = lane >> 2, q = lane & 3;

    // direct store: out[i][j]
#pragma unroll
    for (int mf = 0; mf < 2; mf++) {
#pragma unroll
        for (int rr = 0; rr < 2; rr++) {
            int i = i0 + warp_m * 32 + mf * 16 + g + rr * 8;
            if (i < n) {
#pragma unroll
                for (int nf = 0; nf < 4; nf++) {
                    int j = j0 + warp_n * 32 + nf * 8 + q * 2;
                    if (j + 1 < n) {
                        *(float2*)&out[(size_t)i * n + j] =
                            make_float2(acc[mf][nf][rr * 2], acc[mf][nf][rr * 2 + 1]);
                    } else if (j < n) {
                        out[(size_t)i * n + j] = acc[mf][nf][rr * 2];
                    }
                }
            }
        }
    }

    // mirror store via smem transpose: out[j][i], smt[128 j][68 i] fp32
    if (bi != bj) {
        __syncthreads();
        float* smt = (float*)smem_raw;
#pragma unroll
        for (int mf = 0; mf < 2; mf++) {
            int irel_base = warp_m * 32 + mf * 16 + g;
#pragma unroll
            for (int nf = 0; nf < 4; nf++) {
                int jrel = warp_n * 32 + nf * 8 + q * 2;
                smt[(jrel)     * 68 + irel_base]     = acc[mf][nf][0];
                smt[(jrel + 1) * 68 + irel_base]     = acc[mf][nf][1];
                smt[(jrel)     * 68 + irel_base + 8] = acc[mf][nf][2];
                smt[(jrel + 1) * 68 + irel_base + 8] = acc[mf][nf][3];
            }
        }
        __syncthreads();
        for (int c = tid; c < 128 * 16; c += 256) {
            int jr = c >> 4;
            int i4 = (c & 15) * 4;
            int gi = i0 + i4;
            size_t off = (size_t)(j0 + jr) * n + gi;
            float4 v = *(const float4*)&smt[jr * 68 + i4];
            if (gi + 3 < n) {
                *(float4*)&out[off] = v;
            } else {
                float a[4] = {v.x, v.y, v.z, v.w};
#pragma unroll
                for (int u = 0; u < 4; u++)
                    if (gi + u < n) out[off + u] = a[u];
            }
        }
    }
}

// ---------------- launch ----------------
extern "C" void kernel_launch(void* const* d_in, const int* in_sizes, int n_in,
                              void* d_out, int out_size) {
    const float* features = (const float*)d_in[0];
    const int*   src      = (const int*)d_in[1];
    const int*   dst      = (const int*)d_in[2];
    const float* noise    = (const float*)d_in[3];
    const float* W1       = (const float*)d_in[4];
    const float* b1       = (const float*)d_in[5];
    const float* W2       = (const float*)d_in[6];
    const float* b2       = (const float*)d_in[7];
    const float* W3       = (const float*)d_in[8];
    const float* b3       = (const float*)d_in[9];
    int N = in_sizes[0] / IN_DIM;
    int E = in_sizes[1];
    float* out = (float*)d_out;

    cudaFuncSetAttribute(final_kernel, cudaFuncAttributeMaxDynamicSharedMemorySize, SM_TOTAL);
    cudaFuncSetAttribute(gemm1_hmma, cudaFuncAttributeMaxDynamicSharedMemorySize, G_TOTAL);
    cudaFuncSetAttribute(gemm23_hmma, cudaFuncAttributeMaxDynamicSharedMemorySize, G_TOTAL);

    zero_kernel<<<(N + 255) / 256, 256>>>(N);
    degree_kernel<<<(E + 255) / 256, 256>>>(src, dst, E);
    rs_alloc_kernel<<<(N + 255) / 256, 256>>>(N);
    perm_kernel<<<(E + 255) / 256, 256>>>(src, dst, E);
    convw_kernel<<<(H1 * IN_DIM + H1 * H1 + 255) / 256, 256>>>(W1, W2, W3);

    dim3 gg((N + 127) / 128, 2);
    gemm1_hmma<<<gg, 256, G_TOTAL>>>(features, N);
    agg1_kernel<<<N, 256>>>(b1);
    gemm23_hmma<<<gg, 256, G_TOTAL>>>(N);
    aggz_kernel<<<N, 256>>>(b2, b3, noise);

    int T = (N + 127) / 128;
    final_kernel<<<T * (T + 1), 256, SM_TOTAL>>>(out, N);
}

// round 16
// speedup vs baseline: 1.2487x; 1.0659x over previous
#include <cuda_runtime.h>
#include <cuda_bf16.h>
#include <cstdint>

#define MAXN 10000
#define MAXE 320000
#define IN_DIM 512
#define H1 256
#define H2 128

// ---------------- scratch (device globals; no allocation allowed) ----------------
__device__ int   g_deg_out[MAXN];
__device__ int   g_deg_in[MAXN];
__device__ int   g_cnt[MAXN];
__device__ int   g_alloc;
__device__ float g_rs_out[MAXN];
__device__ float g_rs_in[MAXN];
__device__ int   g_row_off[MAXN];
__device__ int   g_perm_src[MAXE];
__device__ float g_y1[MAXN * H1];    // (x*rs_out) @ W1
__device__ float g_y23[MAXN * H1];   // (h*rs_out) @ [W2|W3]
__device__ __align__(16) __nv_bfloat16 g_ha_hi[MAXN * H1];  // (h*rs_out) bf16 hi
__device__ __align__(16) __nv_bfloat16 g_ha_lo[MAXN * H1];  // (h*rs_out) bf16 lo
__device__ __align__(16) __nv_bfloat16 g_w1t_hi[H1 * IN_DIM];   // W1^T [256][512]
__device__ __align__(16) __nv_bfloat16 g_w1t_lo[H1 * IN_DIM];
__device__ __align__(16) __nv_bfloat16 g_w23t_hi[H1 * H1];      // [W2|W3]^T [256][256]
__device__ __align__(16) __nv_bfloat16 g_w23t_lo[H1 * H1];
__device__ __align__(16) __nv_bfloat16 g_zhi[MAXN * H2];
__device__ __align__(16) __nv_bfloat16 g_zlo[MAXN * H2];

// ---------------- helpers ----------------
__device__ __forceinline__ float sigm(float x) {
    return 1.0f / (1.0f + __expf(-x));
}
__device__ __forceinline__ void bsplit(float v, __nv_bfloat16& hi, __nv_bfloat16& lo) {
    hi = __float2bfloat16(v);
    lo = __float2bfloat16(v - __bfloat162float(hi));
}
__device__ __forceinline__ uint32_t smem_u32(const void* p) {
    uint32_t a;
    asm("{ .reg .u64 t; cvta.to.shared.u64 t, %1; cvt.u32.u64 %0, t; }" : "=r"(a) : "l"(p));
    return a;
}
__device__ __forceinline__ void ldsm_x4(uint32_t a[4], uint32_t addr) {
    asm volatile("ldmatrix.sync.aligned.m8n8.x4.shared.b16 {%0,%1,%2,%3}, [%4];"
        : "=r"(a[0]), "=r"(a[1]), "=r"(a[2]), "=r"(a[3]) : "r"(addr));
}
__device__ __forceinline__ void ldsm_x2(uint32_t b[2], uint32_t addr) {
    asm volatile("ldmatrix.sync.aligned.m8n8.x2.shared.b16 {%0,%1}, [%2];"
        : "=r"(b[0]), "=r"(b[1]) : "r"(addr));
}
__device__ __forceinline__ void mma_bf16(float d[4], const uint32_t a[4], const uint32_t b[2]) {
    asm volatile("mma.sync.aligned.m16n8k16.row.col.f32.bf16.bf16.f32 "
        "{%0,%1,%2,%3}, {%4,%5,%6,%7}, {%8,%9}, {%0,%1,%2,%3};"
        : "+f"(d[0]), "+f"(d[1]), "+f"(d[2]), "+f"(d[3])
        : "r"(a[0]), "r"(a[1]), "r"(a[2]), "r"(a[3]), "r"(b[0]), "r"(b[1]));
}
__device__ __forceinline__ uint32_t pack_bf2(__nv_bfloat16 a, __nv_bfloat16 b) {
    __nv_bfloat162 v(a, b);
    return *(uint32_t*)&v;
}

// ---------------- small setup kernels ----------------
__global__ void zero_kernel(int n) {
    int i = blockIdx.x * blockDim.x + threadIdx.x;
    if (i < n) { g_deg_out[i] = 0; g_deg_in[i] = 0; g_cnt[i] = 0; }
    if (i == 0) g_alloc = 0;
}

__global__ void degree_kernel(const int* __restrict__ src, const int* __restrict__ dst, int e) {
    int i = blockIdx.x * blockDim.x + threadIdx.x;
    if (i < e) {
        atomicAdd(&g_deg_out[src[i]], 1);
        atomicAdd(&g_deg_in[dst[i]], 1);
    }
}

__global__ void rs_alloc_kernel(int n) {
    int i = blockIdx.x * blockDim.x + threadIdx.x;
    if (i < n) {
        int dIn = g_deg_in[i];
        g_rs_out[i] = rsqrtf(fmaxf((float)g_deg_out[i], 1.0f));
        g_rs_in[i]  = rsqrtf(fmaxf((float)dIn, 1.0f));
        g_row_off[i] = atomicAdd(&g_alloc, dIn);
    }
}

__global__ void perm_kernel(const int* __restrict__ src, const int* __restrict__ dst, int e) {
    int i = blockIdx.x * blockDim.x + threadIdx.x;
    if (i < e) {
        int d = dst[i];
        int pos = atomicAdd(&g_cnt[d], 1);
        g_perm_src[g_row_off[d] + pos] = src[i];
    }
}

// one-shot weight transpose + bf16 hi/lo split
__global__ void convw_kernel(const float* __restrict__ W1, const float* __restrict__ W2,
                             const float* __restrict__ W3) {
    int idx = blockIdx.x * blockDim.x + threadIdx.x;
    if (idx < H1 * IN_DIM) {
        int nn = idx >> 9, k = idx & 511;
        __nv_bfloat16 hi, lo;
        bsplit(W1[k * H1 + nn], hi, lo);
        g_w1t_hi[idx] = hi;
        g_w1t_lo[idx] = lo;
    } else {
        int j = idx - H1 * IN_DIM;
        if (j < H1 * H1) {
            int nn = j >> 8, k = j & 255;
            float v = (nn < H2) ? W2[k * H2 + nn] : W3[k * H2 + (nn - H2)];
            __nv_bfloat16 hi, lo;
            bsplit(v, hi, lo);
            g_w23t_hi[j] = hi;
            g_w23t_lo[j] = lo;
        }
    }
}

// ---------------- HMMA GEMM smem geometry ----------------
#define ROWB_G 144
#define GBUF (128 * ROWB_G)
#define GA_HI 0
#define GA_LO GBUF
#define GB_HI (2 * GBUF)
#define GB_LO (3 * GBUF)
#define G_TOTAL (4 * GBUF)             // 73728

// ---------------- GEMM1: y1 = (X*rs_out) @ W1 ----------------
__global__ void __launch_bounds__(256) gemm1_hmma(const float* __restrict__ X, int M) {
    extern __shared__ char smem_raw[];
    int tid = threadIdx.x;
    int w = tid >> 5, lane = tid & 31;
    int m0 = blockIdx.x * 128, n0 = blockIdx.y * 128;
    uint32_t smb = smem_u32(smem_raw);
    int warp_m = w & 1, warp_n = w >> 1;
    uint32_t aoffA = (uint32_t)((warp_m * 64 + (lane & 15)) * ROWB_G + (lane >> 4) * 16);
    uint32_t aoffB = (uint32_t)((warp_n * 32 + (lane & 7)) * ROWB_G + ((lane >> 3) & 1) * 16);

    float acc[4][4][4] = {};

    for (int ch = 0; ch < IN_DIM / 64; ch++) {
        int k0 = ch * 64;
        __syncthreads();
#pragma unroll
        for (int q = 0; q < 8; q++) {
            int idx = q * 256 + tid;
            int row = idx >> 4, c4 = (idx & 15) * 4;
            int gi = m0 + row;
            float4 v = make_float4(0.f, 0.f, 0.f, 0.f);
            float ro = 0.f;
            if (gi < M) { v = *(const float4*)&X[gi * IN_DIM + k0 + c4]; ro = g_rs_out[gi]; }
            __nv_bfloat16 h0, l0, h1, l1, h2, l2, h3, l3;
            bsplit(v.x * ro, h0, l0); bsplit(v.y * ro, h1, l1);
            bsplit(v.z * ro, h2, l2); bsplit(v.w * ro, h3, l3);
            int off = row * ROWB_G + c4 * 2;
            *(uint2*)(smem_raw + GA_HI + off) = make_uint2(pack_bf2(h0, h1), pack_bf2(h2, h3));
            *(uint2*)(smem_raw + GA_LO + off) = make_uint2(pack_bf2(l0, l1), pack_bf2(l2, l3));
        }
#pragma unroll
        for (int q = 0; q < 4; q++) {
            int idx = q * 256 + tid;
            int row = idx >> 3, seg = (idx & 7);
            int off = row * ROWB_G + seg * 16;
            *(uint4*)(smem_raw + GB_HI + off) = *(const uint4*)&g_w1t_hi[(n0 + row) * IN_DIM + k0 + seg * 8];
            *(uint4*)(smem_raw + GB_LO + off) = *(const uint4*)&g_w1t_lo[(n0 + row) * IN_DIM + k0 + seg * 8];
        }
        __syncthreads();
#pragma unroll
        for (int ks = 0; ks < 4; ks++) {
            uint32_t k2 = (uint32_t)(ks * 32);
            uint32_t Ahi[4][4], Bhi[4][2], Blo[4][2];
#pragma unroll
            for (int mf = 0; mf < 4; mf++)
                ldsm_x4(Ahi[mf], smb + GA_HI + aoffA + mf * (16 * ROWB_G) + k2);
#pragma unroll
            for (int nf = 0; nf < 4; nf++) {
                ldsm_x2(Bhi[nf], smb + GB_HI + aoffB + nf * (8 * ROWB_G) + k2);
                ldsm_x2(Blo[nf], smb + GB_LO + aoffB + nf * (8 * ROWB_G) + k2);
            }
#pragma unroll
            for (int mf = 0; mf < 4; mf++)
#pragma unroll
                for (int nf = 0; nf < 4; nf++) {
                    mma_bf16(acc[mf][nf], Ahi[mf], Bhi[nf]);
                    mma_bf16(acc[mf][nf], Ahi[mf], Blo[nf]);
                }
            uint32_t Alo[4][4];
#pragma unroll
            for (int mf = 0; mf < 4; mf++)
                ldsm_x4(Alo[mf], smb + GA_LO + aoffA + mf * (16 * ROWB_G) + k2);
#pragma unroll
            for (int mf = 0; mf < 4; mf++)
#pragma unroll
                for (int nf = 0; nf < 4; nf++)
                    mma_bf16(acc[mf][nf], Alo[mf], Bhi[nf]);
        }
    }
    int g = lane >> 2, q = lane & 3;
#pragma unroll
    for (int mf = 0; mf < 4; mf++)
#pragma unroll
        for (int rr = 0; rr < 2; rr++) {
            int i = m0 + warp_m * 64 + mf * 16 + g + rr * 8;
            if (i < M) {
#pragma unroll
                for (int nf = 0; nf < 4; nf++) {
                    int j = n0 + warp_n * 32 + nf * 8 + q * 2;
                    *(float2*)&g_y1[i * H1 + j] =
                        make_float2(acc[mf][nf][rr * 2], acc[mf][nf][rr * 2 + 1]);
                }
            }
        }
}

// ---------------- GEMM23: y23 = (h*rs_out) @ [W2|W3] ----------------
__global__ void __launch_bounds__(256) gemm23_hmma(int M) {
    extern __shared__ char smem_raw[];
    int tid = threadIdx.x;
    int w = tid >> 5, lane = tid & 31;
    int m0 = blockIdx.x * 128, n0 = blockIdx.y * 128;
    uint32_t smb = smem_u32(smem_raw);
    int warp_m = w & 1, warp_n = w >> 1;
    uint32_t aoffA = (uint32_t)((warp_m * 64 + (lane & 15)) * ROWB_G + (lane >> 4) * 16);
    uint32_t aoffB = (uint32_t)((warp_n * 32 + (lane & 7)) * ROWB_G + ((lane >> 3) & 1) * 16);

    float acc[4][4][4] = {};
    const uint4 zz = make_uint4(0u, 0u, 0u, 0u);

    for (int ch = 0; ch < H1 / 64; ch++) {
        int k0 = ch * 64;
        __syncthreads();
#pragma unroll
        for (int q = 0; q < 4; q++) {
            int idx = q * 256 + tid;
            int row = idx >> 3, seg = (idx & 7);
            int off = row * ROWB_G + seg * 16;
            int gi = m0 + row;
            uint4 ahi = zz, alo = zz;
            if (gi < M) {
                ahi = *(const uint4*)&g_ha_hi[gi * H1 + k0 + seg * 8];
                alo = *(const uint4*)&g_ha_lo[gi * H1 + k0 + seg * 8];
            }
            *(uint4*)(smem_raw + GA_HI + off) = ahi;
            *(uint4*)(smem_raw + GA_LO + off) = alo;
            *(uint4*)(smem_raw + GB_HI + off) = *(const uint4*)&g_w23t_hi[(n0 + row) * H1 + k0 + seg * 8];
            *(uint4*)(smem_raw + GB_LO + off) = *(const uint4*)&g_w23t_lo[(n0 + row) * H1 + k0 + seg * 8];
        }
        __syncthreads();
#pragma unroll
        for (int ks = 0; ks < 4; ks++) {
            uint32_t k2 = (uint32_t)(ks * 32);
            uint32_t Ahi[4][4], Bhi[4][2], Blo[4][2];
#pragma unroll
            for (int mf = 0; mf < 4; mf++)
                ldsm_x4(Ahi[mf], smb + GA_HI + aoffA + mf * (16 * ROWB_G) + k2);
#pragma unroll
            for (int nf = 0; nf < 4; nf++) {
                ldsm_x2(Bhi[nf], smb + GB_HI + aoffB + nf * (8 * ROWB_G) + k2);
                ldsm_x2(Blo[nf], smb + GB_LO + aoffB + nf * (8 * ROWB_G) + k2);
            }
#pragma unroll
            for (int mf = 0; mf < 4; mf++)
#pragma unroll
                for (int nf = 0; nf < 4; nf++) {
                    mma_bf16(acc[mf][nf], Ahi[mf], Bhi[nf]);
                    mma_bf16(acc[mf][nf], Ahi[mf], Blo[nf]);
                }
            uint32_t Alo[4][4];
#pragma unroll
            for (int mf = 0; mf < 4; mf++)
                ldsm_x4(Alo[mf], smb + GA_LO + aoffA + mf * (16 * ROWB_G) + k2);
#pragma unroll
            for (int mf = 0; mf < 4; mf++)
#pragma unroll
                for (int nf = 0; nf < 4; nf++)
                    mma_bf16(acc[mf][nf], Alo[mf], Bhi[nf]);
        }
    }
    int g = lane >> 2, q = lane & 3;
#pragma unroll
    for (int mf = 0; mf < 4; mf++)
#pragma unroll
        for (int rr = 0; rr < 2; rr++) {
            int i = m0 + warp_m * 64 + mf * 16 + g + rr * 8;
            if (i < M) {
#pragma unroll
                for (int nf = 0; nf < 4; nf++) {
                    int j = n0 + warp_n * 32 + nf * 8 + q * 2;
                    *(float2*)&g_y23[i * H1 + j] =
                        make_float2(acc[mf][nf][rr * 2], acc[mf][nf][rr * 2 + 1]);
                }
            }
        }
}

// ---------------- agg1: unroll-4 float2 gather (R12 shape); emit (h*rs_out) bf16 ----------------
__global__ void agg1_kernel(const float* __restrict__ b1) {
    int d = blockIdx.x, t = threadIdx.x;   // 128 threads, 2 cols each
    int s = g_row_off[d], e = s + g_deg_in[d];
    const float2* Y = (const float2*)g_y1;
    float2 a0 = make_float2(0.f, 0.f), a1 = a0, a2 = a0, a3 = a0;
    int i = s;
    for (; i + 3 < e; i += 4) {
        int s0 = g_perm_src[i], s1 = g_perm_src[i + 1];
        int s2 = g_perm_src[i + 2], s3 = g_perm_src[i + 3];
        float2 v0 = Y[s0 * (H1 / 2) + t];
        float2 v1 = Y[s1 * (H1 / 2) + t];
        float2 v2 = Y[s2 * (H1 / 2) + t];
        float2 v3 = Y[s3 * (H1 / 2) + t];
        a0.x += v0.x; a0.y += v0.y;
        a1.x += v1.x; a1.y += v1.y;
        a2.x += v2.x; a2.y += v2.y;
        a3.x += v3.x; a3.y += v3.y;
    }
    for (; i < e; i++) {
        int sn = g_perm_src[i];
        float2 v = Y[sn * (H1 / 2) + t];
        a0.x += v.x; a0.y += v.y;
    }
    float ax = (a0.x + a1.x) + (a2.x + a3.x);
    float ay = (a0.y + a1.y) + (a2.y + a3.y);
    float ri = g_rs_in[d];
    float ro = g_rs_out[d];
    float h0 = fmaxf(ax * ri + b1[2 * t], 0.f) * ro;
    float h1 = fmaxf(ay * ri + b1[2 * t + 1], 0.f) * ro;
    __nv_bfloat16 hi0, lo0, hi1, lo1;
    bsplit(h0, hi0, lo0);
    bsplit(h1, hi1, lo1);
    ((uint32_t*)g_ha_hi)[d * (H1 / 2) + t] = pack_bf2(hi0, hi1);
    ((uint32_t*)g_ha_lo)[d * (H1 / 2) + t] = pack_bf2(lo0, lo1);
}

// ---------------- aggz: unroll-4 float2 gather (R12 shape); z split ----------------
__global__ void aggz_kernel(const float* __restrict__ b2, const float* __restrict__ b3,
                            const float* __restrict__ noise) {
    __shared__ float sm[H1];
    int d = blockIdx.x, t = threadIdx.x;   // 128 threads
    int s = g_row_off[d], e = s + g_deg_in[d];
    const float2* Y = (const float2*)g_y23;
    float2 a0 = make_float2(0.f, 0.f), a1 = a0, a2 = a0, a3 = a0;
    int i = s;
    for (; i + 3 < e; i += 4) {
        int s0 = g_perm_src[i], s1 = g_perm_src[i + 1];
        int s2 = g_perm_src[i + 2], s3 = g_perm_src[i + 3];
        float2 v0 = Y[s0 * (H1 / 2) + t];
        float2 v1 = Y[s1 * (H1 / 2) + t];
        float2 v2 = Y[s2 * (H1 / 2) + t];
        float2 v3 = Y[s3 * (H1 / 2) + t];
        a0.x += v0.x; a0.y += v0.y;
        a1.x += v1.x; a1.y += v1.y;
        a2.x += v2.x; a2.y += v2.y;
        a3.x += v3.x; a3.y += v3.y;
    }
    for (; i < e; i++) {
        int sn = g_perm_src[i];
        float2 v = Y[sn * (H1 / 2) + t];
        a0.x += v.x; a0.y += v.y;
    }
    float ax = (a0.x + a1.x) + (a2.x + a3.x);
    float ay = (a0.y + a1.y) + (a2.y + a3.y);
    float ri = g_rs_in[d];
    sm[2 * t] = ax * ri;
    sm[2 * t + 1] = ay * ri;
    __syncthreads();
    if (t < 64) {
#pragma unroll
        for (int q = 0; q < 2; q++) {
            int c = 2 * t + q;
            float mean = sm[c] + b2[c];
            float ls = sm[c + H2] + b3[c];
            float zv = mean + noise[d * H2 + c] * expf(ls);
            __nv_bfloat16 hi, lo;
            bsplit(zv, hi, lo);
            g_zhi[d * H2 + c] = hi;
            g_zlo[d * H2 + c] = lo;
        }
    }
}

// ---------------- final decoder: mma.sync bf16 hi/lo, 64x128 half-tiles, 2 CTA/SM ----------------
#define ROWB 272
#define IBUF (64 * ROWB)                 // 17408
#define JBUF (128 * ROWB)                // 34816
#define SM_HI_I 0
#define SM_LO_I (IBUF)
#define SM_HI_J (2 * IBUF)
#define SM_LO_J (2 * IBUF + JBUF)
#define SM_TOTAL (2 * IBUF + 2 * JBUF)   // 104448 -> 2 CTAs/SM

__global__ void __launch_bounds__(256) final_kernel(float* __restrict__ out, int n) {
    extern __shared__ char smem_raw[];
    int tid = threadIdx.x;
    int w = tid >> 5, lane = tid & 31;

    int x = blockIdx.x;
    int p = x >> 1, half = x & 1;
    int bi = (int)((sqrtf(8.0f * (float)p + 1.0f) - 1.0f) * 0.5f);
    while ((bi + 1) * (bi + 2) / 2 <= p) bi++;
    while (bi * (bi + 1) / 2 > p) bi--;
    int bj = p - bi * (bi + 1) / 2;
    int i0 = bi * 128 + half * 64;       // 64-row i half-tile
    int j0 = bj * 128;                   // 128-col j tile

    const uint4 zz = make_uint4(0u, 0u, 0u, 0u);
    for (int c = tid; c < 2048; c += 256) {
        int row = c >> 4, seg = c & 15;
        int off = row * ROWB + seg * 16;
        int gj = j0 + row;
        uint4 hi_j = zz, lo_j = zz;
        if (gj < n) {
            hi_j = *(const uint4*)&g_zhi[gj * H2 + seg * 8];
            lo_j = *(const uint4*)&g_zlo[gj * H2 + seg * 8];
        }
        *(uint4*)(smem_raw + SM_HI_J + off) = hi_j;
        *(uint4*)(smem_raw + SM_LO_J + off) = lo_j;
        if (row < 64) {
            int gi = i0 + row;
            uint4 hi_i = zz, lo_i = zz;
            if (gi < n) {
                hi_i = *(const uint4*)&g_zhi[gi * H2 + seg * 8];
                lo_i = *(const uint4*)&g_zlo[gi * H2 + seg * 8];
            }
            *(uint4*)(smem_raw + SM_HI_I + off) = hi_i;
            *(uint4*)(smem_raw + SM_LO_I + off) = lo_i;
        }
    }
    __syncthreads();

    uint32_t smb = smem_u32(smem_raw);
    int warp_m = w & 1, warp_n = w >> 1;      // 2 x 4 warp grid; warp tile 32m x 32n
    uint32_t aoffA = (uint32_t)((warp_m * 32 + (lane & 15)) * ROWB + (lane >> 4) * 16);
    uint32_t aoffB = (uint32_t)((warp_n * 32 + (lane & 7)) * ROWB + ((lane >> 3) & 1) * 16);

    float acc[2][4][4] = {};

    for (int ks = 0; ks < 8; ks++) {
        uint32_t k2 = (uint32_t)(ks * 32);
        uint32_t Ahi[2][4], Bhi[4][2], Blo[4][2];
#pragma unroll
        for (int mf = 0; mf < 2; mf++)
            ldsm_x4(Ahi[mf], smb + SM_HI_I + aoffA + mf * (16 * ROWB) + k2);
#pragma unroll
        for (int nf = 0; nf < 4; nf++) {
            ldsm_x2(Bhi[nf], smb + SM_HI_J + aoffB + nf * (8 * ROWB) + k2);
            ldsm_x2(Blo[nf], smb + SM_LO_J + aoffB + nf * (8 * ROWB) + k2);
        }
#pragma unroll
        for (int mf = 0; mf < 2; mf++)
#pragma unroll
            for (int nf = 0; nf < 4; nf++) {
                mma_bf16(acc[mf][nf], Ahi[mf], Bhi[nf]);
                mma_bf16(acc[mf][nf], Ahi[mf], Blo[nf]);
            }
        uint32_t Alo[2][4];
#pragma unroll
        for (int mf = 0; mf < 2; mf++)
            ldsm_x4(Alo[mf], smb + SM_LO_I + aoffA + mf * (16 * ROWB) + k2);
#pragma unroll
        for (int mf = 0; mf < 2; mf++)
#pragma unroll
            for (int nf = 0; nf < 4; nf++)
                mma_bf16(acc[mf][nf], Alo[mf], Bhi[nf]);
    }

#pragma unroll
    for (int mf = 0; mf < 2; mf++)
#pragma unroll
        for (int nf = 0; nf < 4; nf++)
#pragma unroll
            for (int r = 0; r < 4; r++)
                acc[mf][nf][r] = sigm(acc[mf][nf][r]);

    int g = lane >> 2, q = lane & 3;

    // direct store: out[i][j]
#pragma unroll
    for (int mf = 0; mf < 2; mf++) {
#pragma unroll
        for (int rr = 0; rr < 2; rr++) {
            int i = i0 + warp_m * 32 + mf * 16 + g + rr * 8;
            if (i < n) {
#pragma unroll
                for (int nf = 0; nf < 4; nf++) {
                    int j = j0 + warp_n * 32 + nf * 8 + q * 2;
                    if (j + 1 < n) {
                        *(float2*)&out[(size_t)i * n + j] =
                            make_float2(acc[mf][nf][rr * 2], acc[mf][nf][rr * 2 + 1]);
                    } else if (j < n) {
                        out[(size_t)i * n + j] = acc[mf][nf][rr * 2];
                    }
                }
            }
        }
    }

    // mirror store via smem transpose: out[j][i]
    if (bi != bj) {
        __syncthreads();
        float* smt = (float*)smem_raw;
#pragma unroll
        for (int mf = 0; mf < 2; mf++) {
            int irel_base = warp_m * 32 + mf * 16 + g;
#pragma unroll
            for (int nf = 0; nf < 4; nf++) {
                int jrel = warp_n * 32 + nf * 8 + q * 2;
                smt[(jrel)     * 68 + irel_base]     = acc[mf][nf][0];
                smt[(jrel + 1) * 68 + irel_base]     = acc[mf][nf][1];
                smt[(jrel)     * 68 + irel_base + 8] = acc[mf][nf][2];
                smt[(jrel + 1) * 68 + irel_base + 8] = acc[mf][nf][3];
            }
        }
        __syncthreads();
        for (int c = tid; c < 128 * 16; c += 256) {
            int jr = c >> 4;
            int i4 = (c & 15) * 4;
            int gi = i0 + i4;
            size_t off = (size_t)(j0 + jr) * n + gi;
            float4 v = *(const float4*)&smt[jr * 68 + i4];
            if (gi + 3 < n) {
                *(float4*)&out[off] = v;
            } else {
                float a[4] = {v.x, v.y, v.z, v.w};
#pragma unroll
                for (int u = 0; u < 4; u++)
                    if (gi + u < n) out[off + u] = a[u];
            }
        }
    }
}

// ---------------- launch ----------------
extern "C" void kernel_launch(void* const* d_in, const int* in_sizes, int n_in,
                              void* d_out, int out_size) {
    const float* features = (const float*)d_in[0];
    const int*   src      = (const int*)d_in[1];
    const int*   dst      = (const int*)d_in[2];
    const float* noise    = (const float*)d_in[3];
    const float* W1       = (const float*)d_in[4];
    const float* b1       = (const float*)d_in[5];
    const float* W2       = (const float*)d_in[6];
    const float* b2       = (const float*)d_in[7];
    const float* W3       = (const float*)d_in[8];
    const float* b3       = (const float*)d_in[9];
    int N = in_sizes[0] / IN_DIM;
    int E = in_sizes[1];
    float* out = (float*)d_out;

    static int init_done = 0;
    static cudaStream_t side;
    static cudaEvent_t evStart, evRS, evG1;
    if (!init_done) {
        cudaFuncSetAttribute(final_kernel, cudaFuncAttributeMaxDynamicSharedMemorySize, SM_TOTAL);
        cudaFuncSetAttribute(gemm1_hmma, cudaFuncAttributeMaxDynamicSharedMemorySize, G_TOTAL);
        cudaFuncSetAttribute(gemm23_hmma, cudaFuncAttributeMaxDynamicSharedMemorySize, G_TOTAL);
        cudaStreamCreateWithFlags(&side, cudaStreamNonBlocking);
        cudaEventCreateWithFlags(&evStart, cudaEventDisableTiming);
        cudaEventCreateWithFlags(&evRS, cudaEventDisableTiming);
        cudaEventCreateWithFlags(&evG1, cudaEventDisableTiming);
        init_done = 1;
    }

    // fork: side stream handles convw + gemm1; main stream handles graph setup + perm
    cudaEventRecord(evStart, 0);
    cudaStreamWaitEvent(side, evStart, 0);

    // side: weight conversion (independent)
    convw_kernel<<<(H1 * IN_DIM + H1 * H1 + 255) / 256, 256, 0, side>>>(W1, W2, W3);

    // main: degree pipeline
    zero_kernel<<<(N + 255) / 256, 256>>>(N);
    degree_kernel<<<(E + 255) / 256, 256>>>(src, dst, E);
    rs_alloc_kernel<<<(N + 255) / 256, 256>>>(N);
    cudaEventRecord(evRS, 0);

    // side: gemm1 needs rs_out (evRS) + convw (program order on side)
    cudaStreamWaitEvent(side, evRS, 0);
    dim3 gg((N + 127) / 128, 2);
    gemm1_hmma<<<gg, 256, G_TOTAL, side>>>(features, N);
    cudaEventRecord(evG1, side);

    // main: perm runs concurrent with gemm1
    perm_kernel<<<(E + 255) / 256, 256>>>(src, dst, E);

    // join: agg1 needs perm (program order) + gemm1 (evG1)
    cudaStreamWaitEvent(0, evG1, 0);
    agg1_kernel<<<N, 128>>>(b1);
    gemm23_hmma<<<gg, 256, G_TOTAL>>>(N);
    aggz_kernel<<<N, 128>>>(b2, b3, noise);

    int T = (N + 127) / 128;
    final_kernel<<<T * (T + 1), 256, SM_TOTAL>>>(out, N);
}